// round 1
// baseline (speedup 1.0000x reference)
#include <cuda_runtime.h>
#include <math.h>

#define NB   262144
#define H1C  128
#define H2C  256
#define H3C  200
#define GC   25
#define DC   4
#define GDC  100

// Scratch (no allocations allowed) --------------------------------------
__device__ float g_h2 [(size_t)NB * H2C];   // trunk activations after layer 2
__device__ float g_h3 [(size_t)NB * H3C];   // trunk activations after layer 3
__device__ float g_W2T[H1C * H2C];          // W2 transposed: [k][n]
__device__ float g_W3T[H2C * H3C];          // W3 transposed: [k][n]
__device__ float g_WpT[H3C * GDC];          // Wpai transposed: [k][g*4+d]

// ------------------------------------------------------------------ prep
__global__ void k_prep(const float* __restrict__ W2,
                       const float* __restrict__ W3,
                       const float* __restrict__ Wp) {
    int stride = gridDim.x * blockDim.x;
    int i0 = blockIdx.x * blockDim.x + threadIdx.x;
    for (int e = i0; e < H1C * H2C; e += stride) {
        int k = e / H2C, n = e % H2C;
        g_W2T[e] = W2[n * H1C + k];
    }
    for (int e = i0; e < H2C * H3C; e += stride) {
        int k = e / H3C, n = e % H3C;
        g_W3T[e] = W3[n * H2C + k];
    }
    for (int e = i0; e < H3C * GDC; e += stride) {
        int k = e / GDC, gd = e % GDC;
        g_WpT[e] = Wp[gd * H3C + k];
    }
}

// ------------------------------------------------- layer1+layer2 (fused)
// 64 rows per block, 256 threads, 8x8 register tiles over 64x256 output.
__global__ __launch_bounds__(256) void k_l12(const float* __restrict__ x0,
                                             const float* __restrict__ W1,
                                             const float* __restrict__ b1,
                                             const float* __restrict__ b2) {
    extern __shared__ float sm[];
    float* h1s = sm;                 // [64][128]
    float* W2s = sm + 64 * H1C;      // [128][256] (k-major)
    __shared__ float W1s[H1C * 3];
    __shared__ float b1s[H1C];
    __shared__ float b2s[H2C];
    __shared__ float xs[64 * 3];

    const int tid = threadIdx.x;
    const int b0  = blockIdx.x * 64;

    for (int e = tid; e < H1C * 3; e += 256) W1s[e] = W1[e];
    if (tid < H1C) b1s[tid] = b1[tid];
    b2s[tid] = b2[tid];
    for (int e = tid; e < 64 * 3; e += 256) xs[e] = x0[(size_t)b0 * 3 + e];
    {
        float4* dst = (float4*)W2s;
        const float4* src = (const float4*)g_W2T;
        for (int e = tid; e < H1C * H2C / 4; e += 256) dst[e] = src[e];
    }
    __syncthreads();

    // layer 1: h1 = relu(x0 @ W1^T + b1)   (fan-in 3, trivial)
    for (int e = tid; e < 64 * H1C; e += 256) {
        int r = e >> 7, j = e & 127;
        float v = fmaf(xs[r * 3 + 0], W1s[j * 3 + 0],
                  fmaf(xs[r * 3 + 1], W1s[j * 3 + 1],
                  fmaf(xs[r * 3 + 2], W1s[j * 3 + 2], b1s[j])));
        h1s[e] = fmaxf(v, 0.f);
    }
    __syncthreads();

    // layer 2 GEMM: [64 x 256], K = 128
    const int tx = tid & 31, ty = tid >> 5;
    const int r0 = ty * 8, c0 = tx * 8;
    float acc[8][8];
#pragma unroll
    for (int i = 0; i < 8; i++)
#pragma unroll
        for (int j = 0; j < 8; j++) acc[i][j] = 0.f;

    for (int k = 0; k < H1C; k += 4) {
        float4 a[8];
#pragma unroll
        for (int i = 0; i < 8; i++)
            a[i] = *(const float4*)(h1s + (r0 + i) * H1C + k);
#pragma unroll
        for (int kk = 0; kk < 4; kk++) {
            float4 bv0 = *(const float4*)(W2s + (k + kk) * H2C + c0);
            float4 bv1 = *(const float4*)(W2s + (k + kk) * H2C + c0 + 4);
            float bv[8] = {bv0.x, bv0.y, bv0.z, bv0.w, bv1.x, bv1.y, bv1.z, bv1.w};
#pragma unroll
            for (int i = 0; i < 8; i++) {
                float av = kk == 0 ? a[i].x : kk == 1 ? a[i].y
                         : kk == 2 ? a[i].z : a[i].w;
#pragma unroll
                for (int j = 0; j < 8; j++)
                    acc[i][j] = fmaf(av, bv[j], acc[i][j]);
            }
        }
    }

#pragma unroll
    for (int i = 0; i < 8; i++) {
        float o[8];
#pragma unroll
        for (int j = 0; j < 8; j++)
            o[j] = fmaxf(acc[i][j] + b2s[c0 + j], 0.f);
        float* dst = g_h2 + (size_t)(b0 + r0 + i) * H2C + c0;
        *(float4*)dst       = make_float4(o[0], o[1], o[2], o[3]);
        *(float4*)(dst + 4) = make_float4(o[4], o[5], o[6], o[7]);
    }
}

// --------------------------------------------------------------- layer3
// 64 rows per block, 256 threads (25 col-threads active), K=256 in 4 panels.
__global__ __launch_bounds__(256) void k_l3(const float* __restrict__ b3) {
    extern __shared__ float sm[];
    float* h2s = sm;                 // [64][256]
    float* W3s = sm + 64 * H2C;      // [64][200] panel (k-major)
    __shared__ float b3s[H3C];

    const int tid = threadIdx.x;
    const int b0  = blockIdx.x * 64;

    for (int e = tid; e < H3C; e += 256) b3s[e] = b3[e];
    {
        float4* dst = (float4*)h2s;
        const float4* src = (const float4*)(g_h2 + (size_t)b0 * H2C);
        for (int e = tid; e < 64 * H2C / 4; e += 256) dst[e] = src[e];
    }

    const int tx = tid & 31, ty = tid >> 5;
    const int r0 = ty * 8, c0 = tx * 8;
    float acc[8][8];
#pragma unroll
    for (int i = 0; i < 8; i++)
#pragma unroll
        for (int j = 0; j < 8; j++) acc[i][j] = 0.f;

    for (int p = 0; p < 4; p++) {
        __syncthreads();   // also covers initial h2s staging
        {
            float4* dst = (float4*)W3s;
            const float4* src = (const float4*)(g_W3T + p * 64 * H3C);
            for (int e = tid; e < 64 * H3C / 4; e += 256) dst[e] = src[e];
        }
        __syncthreads();
        if (tx < 25) {
            const int kb = p * 64;
            for (int k = 0; k < 64; k += 4) {
                float4 a[8];
#pragma unroll
                for (int i = 0; i < 8; i++)
                    a[i] = *(const float4*)(h2s + (r0 + i) * H2C + kb + k);
#pragma unroll
                for (int kk = 0; kk < 4; kk++) {
                    float4 bv0 = *(const float4*)(W3s + (k + kk) * H3C + c0);
                    float4 bv1 = *(const float4*)(W3s + (k + kk) * H3C + c0 + 4);
                    float bv[8] = {bv0.x, bv0.y, bv0.z, bv0.w,
                                   bv1.x, bv1.y, bv1.z, bv1.w};
#pragma unroll
                    for (int i = 0; i < 8; i++) {
                        float av = kk == 0 ? a[i].x : kk == 1 ? a[i].y
                                 : kk == 2 ? a[i].z : a[i].w;
#pragma unroll
                        for (int j = 0; j < 8; j++)
                            acc[i][j] = fmaf(av, bv[j], acc[i][j]);
                    }
                }
            }
        }
    }

    if (tx < 25) {
#pragma unroll
        for (int i = 0; i < 8; i++) {
            float o[8];
#pragma unroll
            for (int j = 0; j < 8; j++)
                o[j] = fmaxf(acc[i][j] + b3s[c0 + j], 0.f);
            float* dst = g_h3 + (size_t)(b0 + r0 + i) * H3C + c0;
            *(float4*)dst       = make_float4(o[0], o[1], o[2], o[3]);
            *(float4*)(dst + 4) = make_float4(o[4], o[5], o[6], o[7]);
        }
    }
}

// ------------------------------------------- heads + gumbel-argmax + out
__global__ __launch_bounds__(256) void k_heads(
        const float* __restrict__ gumbel, const float* __restrict__ rnd,
        const float* __restrict__ Wmu,  const float* __restrict__ bmu,
        const float* __restrict__ Wsig, const float* __restrict__ bsig,
        const float* __restrict__ bpai, float* __restrict__ out) {
    extern __shared__ float sm[];
    float* h3s = sm;                    // [64][200]
    float* Wps = sm + 64 * H3C;         // [200][100] (k-major pi weights)
    float* lps = Wps + H3C * GDC;       // [64][100]  log(pi + eps)
    __shared__ int   idxs[256];
    __shared__ float bps[GDC];

    const int tid = threadIdx.x;
    const int b0  = blockIdx.x * 64;

    for (int e = tid; e < GDC; e += 256) bps[e] = bpai[e];
    {
        float4* dst = (float4*)h3s;
        const float4* src = (const float4*)(g_h3 + (size_t)b0 * H3C);
        for (int e = tid; e < 64 * H3C / 4; e += 256) dst[e] = src[e];
    }
    {
        float4* dst = (float4*)Wps;
        const float4* src = (const float4*)g_WpT;
        for (int e = tid; e < H3C * GDC / 4; e += 256) dst[e] = src[e];
    }
    __syncthreads();

    // pi GEMM: [64 x 100], K = 200 (8x4 register tiles, 25 col-threads)
    const int tx = tid & 31, ty = tid >> 5;
    if (tx < 25) {
        const int r0 = ty * 8, c0 = tx * 4;
        float acc[8][4];
#pragma unroll
        for (int i = 0; i < 8; i++)
#pragma unroll
            for (int j = 0; j < 4; j++) acc[i][j] = 0.f;

        for (int k = 0; k < H3C; k += 4) {
            float4 a[8];
#pragma unroll
            for (int i = 0; i < 8; i++)
                a[i] = *(const float4*)(h3s + (r0 + i) * H3C + k);
#pragma unroll
            for (int kk = 0; kk < 4; kk++) {
                float4 bv = *(const float4*)(Wps + (k + kk) * GDC + c0);
#pragma unroll
                for (int i = 0; i < 8; i++) {
                    float av = kk == 0 ? a[i].x : kk == 1 ? a[i].y
                             : kk == 2 ? a[i].z : a[i].w;
                    acc[i][0] = fmaf(av, bv.x, acc[i][0]);
                    acc[i][1] = fmaf(av, bv.y, acc[i][1]);
                    acc[i][2] = fmaf(av, bv.z, acc[i][2]);
                    acc[i][3] = fmaf(av, bv.w, acc[i][3]);
                }
            }
        }
#pragma unroll
        for (int i = 0; i < 8; i++)
#pragma unroll
            for (int j = 0; j < 4; j++) {
                int gd = c0 + j;
                float pai = fabsf(acc[i][j] + bps[gd]);
                lps[(r0 + i) * GDC + gd] = logf(pai + 1e-12f);
            }
    }
    __syncthreads();

    // Gumbel-argmax over G for each (row, d); first-max wins (strict >)
    {
        int r = tid >> 2, d = tid & 3;
        const float* gp = gumbel + (size_t)(b0 + r) * (GC * DC) + d;
        float best = -1e30f;
        int bg = 0;
#pragma unroll
        for (int g = 0; g < GC; g++) {
            float v = lps[r * GDC + g * 4 + d] + gp[g * 4];
            if (v > best) { best = v; bg = g; }
        }
        idxs[tid] = bg;
    }
    __syncthreads();

    // Selected mu / sigma: one warp per pair, 32 pairs per warp.
    const int wid = tid >> 5, lane = tid & 31;
    for (int q = 0; q < 32; q++) {
        int p = wid * 32 + q;
        int r = p >> 2, d = p & 3;
        int head = idxs[p] * 4 + d;
        const float4* wm = (const float4*)(Wmu  + (size_t)head * H3C);
        const float4* ws = (const float4*)(Wsig + (size_t)head * H3C);
        const float4* hv = (const float4*)(h3s + r * H3C);   // 50 float4 chunks

        float4 h0 = hv[lane];
        float4 m0 = wm[lane];
        float4 s0 = ws[lane];
        float smu = h0.x * m0.x + h0.y * m0.y + h0.z * m0.z + h0.w * m0.w;
        float ssg = h0.x * s0.x + h0.y * s0.y + h0.z * s0.z + h0.w * s0.w;
        if (lane < 18) {
            float4 h1v = hv[32 + lane];
            float4 m1  = wm[32 + lane];
            float4 s1  = ws[32 + lane];
            smu += h1v.x * m1.x + h1v.y * m1.y + h1v.z * m1.z + h1v.w * m1.w;
            ssg += h1v.x * s1.x + h1v.y * s1.y + h1v.z * s1.z + h1v.w * s1.w;
        }
#pragma unroll
        for (int off = 16; off > 0; off >>= 1) {
            smu += __shfl_xor_sync(0xffffffffu, smu, off);
            ssg += __shfl_xor_sync(0xffffffffu, ssg, off);
        }
        if (lane == 0) {
            float mu = smu + bmu[head];
            float sg = fabsf(ssg + bsig[head]);
            size_t oi = (size_t)(b0 + r) * DC + d;
            out[oi] = rnd[oi] * sg + mu;
        }
    }
}

// ---------------------------------------------------------------- launch
extern "C" void kernel_launch(void* const* d_in, const int* in_sizes, int n_in,
                              void* d_out, int out_size) {
    const float* x0   = (const float*)d_in[0];
    const float* rnd  = (const float*)d_in[1];
    const float* gum  = (const float*)d_in[2];
    const float* W1   = (const float*)d_in[3];
    const float* b1   = (const float*)d_in[4];
    const float* W2   = (const float*)d_in[5];
    const float* b2   = (const float*)d_in[6];
    const float* W3   = (const float*)d_in[7];
    const float* b3   = (const float*)d_in[8];
    const float* Wmu  = (const float*)d_in[9];
    const float* bmu  = (const float*)d_in[10];
    const float* Wsig = (const float*)d_in[11];
    const float* bsig = (const float*)d_in[12];
    const float* Wpai = (const float*)d_in[13];
    const float* bpai = (const float*)d_in[14];
    float* out = (float*)d_out;

    const size_t smA = (size_t)(64 * H1C + H1C * H2C) * sizeof(float);  // 160 KB
    const size_t smB = (size_t)(64 * H2C + 64 * H3C) * sizeof(float);   // 114 KB
    const size_t smC = (size_t)(64 * H3C + H3C * GDC + 64 * GDC) * sizeof(float); // 153 KB

    cudaFuncSetAttribute(k_l12,   cudaFuncAttributeMaxDynamicSharedMemorySize, (int)smA);
    cudaFuncSetAttribute(k_l3,    cudaFuncAttributeMaxDynamicSharedMemorySize, (int)smB);
    cudaFuncSetAttribute(k_heads, cudaFuncAttributeMaxDynamicSharedMemorySize, (int)smC);

    k_prep<<<64, 256>>>(W2, W3, Wpai);
    k_l12 <<<NB / 64, 256, smA>>>(x0, W1, b1, b2);
    k_l3  <<<NB / 64, 256, smB>>>(b3);
    k_heads<<<NB / 64, 256, smC>>>(gum, rnd, Wmu, bmu, Wsig, bsig, bpai, out);
}

// round 2
// speedup vs baseline: 1.0095x; 1.0095x over previous
#include <cuda_runtime.h>
#include <math.h>

#define NB   262144
#define H1C  128
#define H2C  256
#define H3C  200
#define GC   25
#define DC   4
#define GDC  100

// Scratch (no allocations allowed) --------------------------------------
__device__ float g_h2 [(size_t)NB * H2C];   // trunk activations after layer 2
__device__ float g_h3 [(size_t)NB * H3C];   // trunk activations after layer 3
__device__ float g_W2T[H1C * H2C];          // W2 transposed: [k][n]
__device__ float g_W3T[H2C * H3C];          // W3 transposed: [k][n]
__device__ float g_WpT[H3C * GDC];          // Wpai transposed: [k][g*4+d]

// ------------------------------------------------------------------ prep
__global__ void k_prep(const float* __restrict__ W2,
                       const float* __restrict__ W3,
                       const float* __restrict__ Wp) {
    int stride = gridDim.x * blockDim.x;
    int i0 = blockIdx.x * blockDim.x + threadIdx.x;
    for (int e = i0; e < H1C * H2C; e += stride) {
        int k = e / H2C, n = e % H2C;
        g_W2T[e] = W2[n * H1C + k];
    }
    for (int e = i0; e < H2C * H3C; e += stride) {
        int k = e / H3C, n = e % H3C;
        g_W3T[e] = W3[n * H2C + k];
    }
    for (int e = i0; e < H3C * GDC; e += stride) {
        int k = e / GDC, gd = e % GDC;
        g_WpT[e] = Wp[gd * H3C + k];
    }
}

// ------------------------------------------------- layer1+layer2 (fused)
// 64 rows per block, 256 threads, 8x8 register tiles over 64x256 output.
__global__ __launch_bounds__(256) void k_l12(const float* __restrict__ x0,
                                             const float* __restrict__ W1,
                                             const float* __restrict__ b1,
                                             const float* __restrict__ b2) {
    extern __shared__ float sm[];
    float* h1s = sm;                 // [64][128]
    float* W2s = sm + 64 * H1C;      // [128][256] (k-major)
    __shared__ float W1s[H1C * 3];
    __shared__ float b1s[H1C];
    __shared__ float b2s[H2C];
    __shared__ float xs[64 * 3];

    const int tid = threadIdx.x;
    const int b0  = blockIdx.x * 64;

    for (int e = tid; e < H1C * 3; e += 256) W1s[e] = W1[e];
    if (tid < H1C) b1s[tid] = b1[tid];
    b2s[tid] = b2[tid];
    for (int e = tid; e < 64 * 3; e += 256) xs[e] = x0[(size_t)b0 * 3 + e];
    {
        float4* dst = (float4*)W2s;
        const float4* src = (const float4*)g_W2T;
        for (int e = tid; e < H1C * H2C / 4; e += 256) dst[e] = src[e];
    }
    __syncthreads();

    // layer 1: h1 = relu(x0 @ W1^T + b1)   (fan-in 3, trivial)
    for (int e = tid; e < 64 * H1C; e += 256) {
        int r = e >> 7, j = e & 127;
        float v = fmaf(xs[r * 3 + 0], W1s[j * 3 + 0],
                  fmaf(xs[r * 3 + 1], W1s[j * 3 + 1],
                  fmaf(xs[r * 3 + 2], W1s[j * 3 + 2], b1s[j])));
        h1s[e] = fmaxf(v, 0.f);
    }
    __syncthreads();

    // layer 2 GEMM: [64 x 256], K = 128
    const int tx = tid & 31, ty = tid >> 5;
    const int r0 = ty * 8, c0 = tx * 8;
    float acc[8][8];
#pragma unroll
    for (int i = 0; i < 8; i++)
#pragma unroll
        for (int j = 0; j < 8; j++) acc[i][j] = 0.f;

    for (int k = 0; k < H1C; k += 4) {
        float4 a[8];
#pragma unroll
        for (int i = 0; i < 8; i++)
            a[i] = *(const float4*)(h1s + (r0 + i) * H1C + k);
#pragma unroll
        for (int kk = 0; kk < 4; kk++) {
            float4 bv0 = *(const float4*)(W2s + (k + kk) * H2C + c0);
            float4 bv1 = *(const float4*)(W2s + (k + kk) * H2C + c0 + 4);
            float bv[8] = {bv0.x, bv0.y, bv0.z, bv0.w, bv1.x, bv1.y, bv1.z, bv1.w};
#pragma unroll
            for (int i = 0; i < 8; i++) {
                float av = kk == 0 ? a[i].x : kk == 1 ? a[i].y
                         : kk == 2 ? a[i].z : a[i].w;
#pragma unroll
                for (int j = 0; j < 8; j++)
                    acc[i][j] = fmaf(av, bv[j], acc[i][j]);
            }
        }
    }

#pragma unroll
    for (int i = 0; i < 8; i++) {
        float o[8];
#pragma unroll
        for (int j = 0; j < 8; j++)
            o[j] = fmaxf(acc[i][j] + b2s[c0 + j], 0.f);
        float* dst = g_h2 + (size_t)(b0 + r0 + i) * H2C + c0;
        *(float4*)dst       = make_float4(o[0], o[1], o[2], o[3]);
        *(float4*)(dst + 4) = make_float4(o[4], o[5], o[6], o[7]);
    }
}

// --------------------------------------------------------------- layer3
// 64 rows per block, 256 threads (25 col-threads active), K=256 in 4 panels.
__global__ __launch_bounds__(256) void k_l3(const float* __restrict__ b3) {
    extern __shared__ float sm[];
    float* h2s = sm;                 // [64][256]
    float* W3s = sm + 64 * H2C;      // [64][200] panel (k-major)
    __shared__ float b3s[H3C];

    const int tid = threadIdx.x;
    const int b0  = blockIdx.x * 64;

    for (int e = tid; e < H3C; e += 256) b3s[e] = b3[e];
    {
        float4* dst = (float4*)h2s;
        const float4* src = (const float4*)(g_h2 + (size_t)b0 * H2C);
        for (int e = tid; e < 64 * H2C / 4; e += 256) dst[e] = src[e];
    }

    const int tx = tid & 31, ty = tid >> 5;
    const int r0 = ty * 8, c0 = tx * 8;
    float acc[8][8];
#pragma unroll
    for (int i = 0; i < 8; i++)
#pragma unroll
        for (int j = 0; j < 8; j++) acc[i][j] = 0.f;

    for (int p = 0; p < 4; p++) {
        __syncthreads();   // also covers initial h2s staging
        {
            float4* dst = (float4*)W3s;
            const float4* src = (const float4*)(g_W3T + p * 64 * H3C);
            for (int e = tid; e < 64 * H3C / 4; e += 256) dst[e] = src[e];
        }
        __syncthreads();
        if (tx < 25) {
            const int kb = p * 64;
            for (int k = 0; k < 64; k += 4) {
                float4 a[8];
#pragma unroll
                for (int i = 0; i < 8; i++)
                    a[i] = *(const float4*)(h2s + (r0 + i) * H2C + kb + k);
#pragma unroll
                for (int kk = 0; kk < 4; kk++) {
                    float4 bv0 = *(const float4*)(W3s + (k + kk) * H3C + c0);
                    float4 bv1 = *(const float4*)(W3s + (k + kk) * H3C + c0 + 4);
                    float bv[8] = {bv0.x, bv0.y, bv0.z, bv0.w,
                                   bv1.x, bv1.y, bv1.z, bv1.w};
#pragma unroll
                    for (int i = 0; i < 8; i++) {
                        float av = kk == 0 ? a[i].x : kk == 1 ? a[i].y
                                 : kk == 2 ? a[i].z : a[i].w;
#pragma unroll
                        for (int j = 0; j < 8; j++)
                            acc[i][j] = fmaf(av, bv[j], acc[i][j]);
                    }
                }
            }
        }
    }

    if (tx < 25) {
#pragma unroll
        for (int i = 0; i < 8; i++) {
            float o[8];
#pragma unroll
            for (int j = 0; j < 8; j++)
                o[j] = fmaxf(acc[i][j] + b3s[c0 + j], 0.f);
            float* dst = g_h3 + (size_t)(b0 + r0 + i) * H3C + c0;
            *(float4*)dst       = make_float4(o[0], o[1], o[2], o[3]);
            *(float4*)(dst + 4) = make_float4(o[4], o[5], o[6], o[7]);
        }
    }
}

// ------------------------------------------- heads + gumbel-argmax + out
__global__ __launch_bounds__(256) void k_heads(
        const float* __restrict__ gumbel, const float* __restrict__ rnd,
        const float* __restrict__ Wmu,  const float* __restrict__ bmu,
        const float* __restrict__ Wsig, const float* __restrict__ bsig,
        const float* __restrict__ bpai, float* __restrict__ out) {
    extern __shared__ float sm[];
    float* h3s = sm;                    // [64][200]
    float* Wps = sm + 64 * H3C;         // [200][100] (k-major pi weights)
    float* lps = Wps + H3C * GDC;       // [64][100]  log(pi + eps)
    __shared__ int   idxs[256];
    __shared__ float bps[GDC];

    const int tid = threadIdx.x;
    const int b0  = blockIdx.x * 64;

    for (int e = tid; e < GDC; e += 256) bps[e] = bpai[e];
    {
        float4* dst = (float4*)h3s;
        const float4* src = (const float4*)(g_h3 + (size_t)b0 * H3C);
        for (int e = tid; e < 64 * H3C / 4; e += 256) dst[e] = src[e];
    }
    {
        float4* dst = (float4*)Wps;
        const float4* src = (const float4*)g_WpT;
        for (int e = tid; e < H3C * GDC / 4; e += 256) dst[e] = src[e];
    }
    __syncthreads();

    // pi GEMM: [64 x 100], K = 200 (8x4 register tiles, 25 col-threads)
    const int tx = tid & 31, ty = tid >> 5;
    if (tx < 25) {
        const int r0 = ty * 8, c0 = tx * 4;
        float acc[8][4];
#pragma unroll
        for (int i = 0; i < 8; i++)
#pragma unroll
            for (int j = 0; j < 4; j++) acc[i][j] = 0.f;

        for (int k = 0; k < H3C; k += 4) {
            float4 a[8];
#pragma unroll
            for (int i = 0; i < 8; i++)
                a[i] = *(const float4*)(h3s + (r0 + i) * H3C + k);
#pragma unroll
            for (int kk = 0; kk < 4; kk++) {
                float4 bv = *(const float4*)(Wps + (k + kk) * GDC + c0);
#pragma unroll
                for (int i = 0; i < 8; i++) {
                    float av = kk == 0 ? a[i].x : kk == 1 ? a[i].y
                             : kk == 2 ? a[i].z : a[i].w;
                    acc[i][0] = fmaf(av, bv.x, acc[i][0]);
                    acc[i][1] = fmaf(av, bv.y, acc[i][1]);
                    acc[i][2] = fmaf(av, bv.z, acc[i][2]);
                    acc[i][3] = fmaf(av, bv.w, acc[i][3]);
                }
            }
        }
#pragma unroll
        for (int i = 0; i < 8; i++)
#pragma unroll
            for (int j = 0; j < 4; j++) {
                int gd = c0 + j;
                float pai = fabsf(acc[i][j] + bps[gd]);
                lps[(r0 + i) * GDC + gd] = logf(pai + 1e-12f);
            }
    }
    __syncthreads();

    // Gumbel-argmax over G for each (row, d); first-max wins (strict >)
    {
        int r = tid >> 2, d = tid & 3;
        const float* gp = gumbel + (size_t)(b0 + r) * (GC * DC) + d;
        float best = -1e30f;
        int bg = 0;
#pragma unroll
        for (int g = 0; g < GC; g++) {
            float v = lps[r * GDC + g * 4 + d] + gp[g * 4];
            if (v > best) { best = v; bg = g; }
        }
        idxs[tid] = bg;
    }
    __syncthreads();

    // Selected mu / sigma: one warp per pair, 32 pairs per warp.
    const int wid = tid >> 5, lane = tid & 31;
    for (int q = 0; q < 32; q++) {
        int p = wid * 32 + q;
        int r = p >> 2, d = p & 3;
        int head = idxs[p] * 4 + d;
        const float4* wm = (const float4*)(Wmu  + (size_t)head * H3C);
        const float4* ws = (const float4*)(Wsig + (size_t)head * H3C);
        const float4* hv = (const float4*)(h3s + r * H3C);   // 50 float4 chunks

        float4 h0 = hv[lane];
        float4 m0 = wm[lane];
        float4 s0 = ws[lane];
        float smu = h0.x * m0.x + h0.y * m0.y + h0.z * m0.z + h0.w * m0.w;
        float ssg = h0.x * s0.x + h0.y * s0.y + h0.z * s0.z + h0.w * s0.w;
        if (lane < 18) {
            float4 h1v = hv[32 + lane];
            float4 m1  = wm[32 + lane];
            float4 s1  = ws[32 + lane];
            smu += h1v.x * m1.x + h1v.y * m1.y + h1v.z * m1.z + h1v.w * m1.w;
            ssg += h1v.x * s1.x + h1v.y * s1.y + h1v.z * s1.z + h1v.w * s1.w;
        }
#pragma unroll
        for (int off = 16; off > 0; off >>= 1) {
            smu += __shfl_xor_sync(0xffffffffu, smu, off);
            ssg += __shfl_xor_sync(0xffffffffu, ssg, off);
        }
        if (lane == 0) {
            float mu = smu + bmu[head];
            float sg = fabsf(ssg + bsig[head]);
            size_t oi = (size_t)(b0 + r) * DC + d;
            out[oi] = rnd[oi] * sg + mu;
        }
    }
}

// ---------------------------------------------------------------- launch
extern "C" void kernel_launch(void* const* d_in, const int* in_sizes, int n_in,
                              void* d_out, int out_size) {
    const float* x0   = (const float*)d_in[0];
    const float* rnd  = (const float*)d_in[1];
    const float* gum  = (const float*)d_in[2];
    const float* W1   = (const float*)d_in[3];
    const float* b1   = (const float*)d_in[4];
    const float* W2   = (const float*)d_in[5];
    const float* b2   = (const float*)d_in[6];
    const float* W3   = (const float*)d_in[7];
    const float* b3   = (const float*)d_in[8];
    const float* Wmu  = (const float*)d_in[9];
    const float* bmu  = (const float*)d_in[10];
    const float* Wsig = (const float*)d_in[11];
    const float* bsig = (const float*)d_in[12];
    const float* Wpai = (const float*)d_in[13];
    const float* bpai = (const float*)d_in[14];
    float* out = (float*)d_out;

    const size_t smA = (size_t)(64 * H1C + H1C * H2C) * sizeof(float);  // 160 KB
    const size_t smB = (size_t)(64 * H2C + 64 * H3C) * sizeof(float);   // 114 KB
    const size_t smC = (size_t)(64 * H3C + H3C * GDC + 64 * GDC) * sizeof(float); // 153 KB

    cudaFuncSetAttribute(k_l12,   cudaFuncAttributeMaxDynamicSharedMemorySize, (int)smA);
    cudaFuncSetAttribute(k_l3,    cudaFuncAttributeMaxDynamicSharedMemorySize, (int)smB);
    cudaFuncSetAttribute(k_heads, cudaFuncAttributeMaxDynamicSharedMemorySize, (int)smC);

    k_prep<<<64, 256>>>(W2, W3, Wpai);
    k_l12 <<<NB / 64, 256, smA>>>(x0, W1, b1, b2);
    k_l3  <<<NB / 64, 256, smB>>>(b3);
    k_heads<<<NB / 64, 256, smC>>>(gum, rnd, Wmu, bmu, Wsig, bsig, bpai, out);
}